// round 16
// baseline (speedup 1.0000x reference)
#include <cuda_runtime.h>
#include <cuda_bf16.h>
#include <cstdint>

// ---------------------------------------------------------------------------
// Problem constants
// ---------------------------------------------------------------------------
namespace {
constexpr int kB   = 64;
constexpr int kS   = 128;
constexpr int kL   = 512;
constexpr int kVEC = 512;
constexpr int kHID = 1024;
constexpr int kRows = kB * kS;          // 8192
constexpr int kOut  = kVEC + kHID;      // 1536

constexpr int NT = 256;                 // 8 warps per GEMM CTA

// Per-mode smem stage layout.
// MODE1: A bf16(256x128B x2 comp) + B fp32 W [k][n] 64 rows x 132 floats
// MODE2: A bf16(128x128B x2 comp) + B fp32 desc [n][k] 256 rows x 68 floats
// MODE3: A bf16(128x128B x2 comp) + B fp32 desc [k][n] 64 rows x 268 floats
template<int MODE> struct Cfg;
template<> struct Cfg<1> {
    static constexpr int AR = 256, A_BYTES = 256 * 128;
    static constexpr int OFF_B = 2 * A_BYTES;
    static constexpr int BROW = 132;                       // floats, 528B
    static constexpr int STG = OFF_B + 64 * BROW * 4;      // 99328
};
template<> struct Cfg<2> {
    static constexpr int AR = 128, A_BYTES = 128 * 128;
    static constexpr int OFF_B = 2 * A_BYTES;
    static constexpr int BROW = 68;                        // floats, 272B
    static constexpr int STG = OFF_B + 256 * BROW * 4;     // 102400
};
template<> struct Cfg<3> {
    static constexpr int AR = 128, A_BYTES = 128 * 128;
    static constexpr int OFF_B = 2 * A_BYTES;
    static constexpr int BROW = 268;                       // floats, 1072B
    static constexpr int STG = OFF_B + 64 * BROW * 4;      // 101376
};
}

// ---------------------------------------------------------------------------
// Device-global scratch (no allocations allowed)
// ---------------------------------------------------------------------------
#define DEVB __device__ __align__(16)
DEVB __nv_bfloat16 g_SKhi[(size_t)kRows * kVEC];
DEVB __nv_bfloat16 g_SKlo[(size_t)kRows * kVEC];
DEVB __nv_bfloat16 g_Qhi [(size_t)kRows * kHID];
DEVB __nv_bfloat16 g_Qlo [(size_t)kRows * kHID];
DEVB float         g_P   [(size_t)kRows * kL];         // scores (fp32)
DEVB __nv_bfloat16 g_Phi [(size_t)kRows * kL];         // attn split
DEVB __nv_bfloat16 g_Plo [(size_t)kRows * kL];

// ---------------------------------------------------------------------------
// Helpers
// ---------------------------------------------------------------------------
__device__ __forceinline__ uint32_t smem_u32(const void* p) {
    uint32_t a;
    asm("{ .reg .u64 t; cvta.to.shared.u64 t, %1; cvt.u32.u64 %0, t; }"
        : "=r"(a) : "l"(p));
    return a;
}
__device__ __forceinline__ uint32_t sw128(uint32_t off) {   // 128B rows
    return off ^ ((off >> 3) & 0x70);
}
__device__ __forceinline__ void ldsm_x4(uint32_t* r, uint32_t addr) {
    asm volatile("ldmatrix.sync.aligned.m8n8.x4.shared.b16 {%0,%1,%2,%3}, [%4];"
                 : "=r"(r[0]), "=r"(r[1]), "=r"(r[2]), "=r"(r[3]) : "r"(addr));
}
__device__ __forceinline__ void mma_bf16(float* c, const uint32_t* a, const uint32_t* b) {
    asm volatile(
        "mma.sync.aligned.m16n8k16.row.col.f32.bf16.bf16.f32 "
        "{%0,%1,%2,%3}, {%4,%5,%6,%7}, {%8,%9}, {%0,%1,%2,%3};"
        : "+f"(c[0]), "+f"(c[1]), "+f"(c[2]), "+f"(c[3])
        : "r"(a[0]), "r"(a[1]), "r"(a[2]), "r"(a[3]), "r"(b[0]), "r"(b[1]));
}
__device__ __forceinline__ void cpa16(uint32_t s, const void* g) {
    asm volatile("cp.async.cg.shared.global [%0], [%1], 16;" :: "r"(s), "l"(g));
}
__device__ __forceinline__ void cpa_commit() {
    asm volatile("cp.async.commit_group;" ::: "memory");
}
__device__ __forceinline__ void cpa_wait1() {
    asm volatile("cp.async.wait_group 1;" ::: "memory");
}
__device__ __forceinline__ void split2(float v, __nv_bfloat16& h, __nv_bfloat16& l) {
    h = __float2bfloat16(v);
    l = __float2bfloat16(v - __bfloat162float(h));
}
__device__ __forceinline__ void split_pack(float a, float b,
                                           uint32_t& hi, uint32_t& lo) {
    __nv_bfloat16 h0, h1, l0, l1;
    split2(a, h0, l0); split2(b, h1, l1);
    __nv_bfloat162 ph, pl;
    ph.x = h0; ph.y = h1; pl.x = l0; pl.y = l1;
    hi = *reinterpret_cast<uint32_t*>(&ph);
    lo = *reinterpret_cast<uint32_t*>(&pl);
}

// ---------------------------------------------------------------------------
// conv_sk: self-probing gather. Detects int64-vs-int32 skills per block
// (odd 32-bit words all zero <=> int64), then gathers emb rows into
// out[:,0:512] fp32 AND g_SKhi/lo bf16 split.
// ---------------------------------------------------------------------------
__global__ void conv_sk(const int* __restrict__ s32,
                        const float* __restrict__ emb,
                        float* __restrict__ out) {
    const int tx = threadIdx.x;               // 128 threads
    // probe: if int64 little-endian, every odd word of the first 64 values is 0
    int w = (tx < 64) ? s32[2 * tx + 1] : 0;
    const int any = __syncthreads_or(w);
    const int row = blockIdx.x;
    const int idx = (any == 0) ? s32[2 * row] : s32[row];

    float4 v = ((const float4*)(emb + (size_t)idx * kVEC))[tx];
    ((float4*)(out + (size_t)row * kOut))[tx] = v;

    uint32_t h01, l01, h23, l23;
    split_pack(v.x, v.y, h01, l01);
    split_pack(v.z, v.w, h23, l23);
    size_t o = (size_t)row * kVEC + tx * 4;
    *(uint2*)(g_SKhi + o) = make_uint2(h01, h23);
    *(uint2*)(g_SKlo + o) = make_uint2(l01, l23);
}

// ---------------------------------------------------------------------------
// Split-bf16 warp-MMA GEMM, cp.async double-buffered, warp tile 64x64.
// All fp32 operands are split into (hi, lo) bf16 at fragment-build time via
// LDS + split_pack; bf16 operands use ldmatrix from sw128 tiles.
// MODE 1: CTA 256x128 (4Mx2N). Q = SK @ W.      B = fp32 W [k][n] (no conv_W).
// MODE 2: CTA 128x256 (2Mx4N). P = Q @ desc^T.  B = fp32 desc [n][k].
// MODE 3: CTA 128x256 (2Mx4N). ctx = attn @ desc. B = fp32 desc [k][n].
// ---------------------------------------------------------------------------
template<int MODE>
__global__ __launch_bounds__(NT, 1) void mma_gemm(float* __restrict__ outP,
                                                  const float* __restrict__ bsrc) {
    using C = Cfg<MODE>;
    extern __shared__ __align__(1024) char smem[];
    const uint32_t sb = smem_u32(smem);
    const int tid = threadIdx.x, wid = tid >> 5, lane = tid & 31;
    const int x = blockIdx.x, y = blockIdx.y;

    constexpr int K = (MODE == 2) ? kHID : kVEC;
    constexpr int STG = C::STG;

    const __nv_bfloat16 *Ahi, *Alo;
    const float* Bf;
    if (MODE == 1) {
        Ahi = g_SKhi + (size_t)y * 256 * K;  Alo = g_SKlo + (size_t)y * 256 * K;
        Bf  = bsrc;                                    // W [k][n], k=VEC rows
    } else if (MODE == 2) {
        Ahi = g_Qhi + (size_t)y * 128 * K;   Alo = g_Qlo + (size_t)y * 128 * K;
        Bf  = bsrc + (size_t)y * kL * kHID + (size_t)x * 256 * kHID;  // [n][k]
    } else {
        Ahi = g_Phi + (size_t)y * 128 * K;   Alo = g_Plo + (size_t)y * 128 * K;
        Bf  = bsrc + (size_t)y * kL * kHID;            // [k][n]
    }

    const int wm = (MODE == 1) ? (wid >> 1) * 64 : (wid >> 2) * 64;
    const int wn = (MODE == 1) ? (wid & 1) * 64  : (wid & 3) * 64;

    auto load_stage = [&](int st, int k0) {
        const uint32_t so = sb + st * STG;
        // A: AR rows x 128B per component, sw128
#pragma unroll
        for (int it = 0; it < C::AR / 32; ++it) {
            const int ch = tid + it * NT;
            const int r = ch >> 3, c = ch & 7;
            const uint32_t d = sw128((uint32_t)(r * 128 + c * 16));
            const size_t go = (size_t)r * K + k0 + c * 8;
            cpa16(so + d, Ahi + go);
            cpa16(so + C::A_BYTES + d, Alo + go);
        }
        if (MODE == 1) {
            // B fp32 W [k][n]: 64 k-rows x 128 n-floats (rows of 528B)
#pragma unroll
            for (int it = 0; it < 8; ++it) {
                const int ch = tid + it * NT;          // 0..2047
                const int r = ch >> 5, c = ch & 31;
                cpa16(so + C::OFF_B + r * 528 + c * 16,
                      Bf + (size_t)(k0 + r) * kHID + x * 128 + c * 4);
            }
        } else if (MODE == 2) {
            // B fp32 [n][k]: 256 rows x 64 floats (rows of 272B)
#pragma unroll
            for (int it = 0; it < 16; ++it) {
                const int ch = tid + it * NT;          // 0..4095
                const int r = ch >> 4, c = ch & 15;
                cpa16(so + C::OFF_B + r * 272 + c * 16,
                      Bf + (size_t)r * kHID + k0 + c * 4);
            }
        } else {
            // B fp32 [k][n]: 64 rows x 256 floats (rows of 1072B)
#pragma unroll
            for (int it = 0; it < 16; ++it) {
                const int ch = tid + it * NT;          // 0..4095
                const int r = ch >> 6, c = ch & 63;
                cpa16(so + C::OFF_B + r * 1072 + c * 16,
                      Bf + (size_t)(k0 + r) * kHID + x * 256 + c * 4);
            }
        }
    };

    float acc[4][8][4] = {};

    constexpr int NCH = K / 64;
    load_stage(0, 0);
    cpa_commit();

    for (int kc = 0; kc < NCH; ++kc) {
        const int st = kc & 1;
        if (kc + 1 < NCH) load_stage(st ^ 1, (kc + 1) * 64);
        cpa_commit();
        cpa_wait1();
        __syncthreads();

        const uint32_t so = sb + st * STG;
        const char* sp = smem + st * STG;
        const float* bs = (const float*)(sp + C::OFF_B);
#pragma unroll
        for (int kk = 0; kk < 4; ++kk) {
            // A fragments: 4 m-tiles x (hi,lo) via ldmatrix
            uint32_t aHi[4][4], aLo[4][4];
#pragma unroll
            for (int i = 0; i < 4; ++i) {
                const int row = wm + i * 16 + (lane & 15);
                const int kb  = kk * 32 + (lane >> 4) * 16;
                const uint32_t d = sw128((uint32_t)(row * 128 + kb));
                ldsm_x4(aHi[i], so + d);
                ldsm_x4(aLo[i], so + C::A_BYTES + d);
            }
            // B per 16-n group: build frags from fp32 smem, fire 24 MMAs.
#pragma unroll
            for (int j4 = 0; j4 < 4; ++j4) {
                uint32_t bHi[2][2], bLo[2][2];
                if (MODE == 1) {
                    // W [k][n] rows of 132 floats (conflict-free strided LDS)
#pragma unroll
                    for (int jj = 0; jj < 2; ++jj) {
                        const int n = wn + j4 * 16 + jj * 8 + (lane >> 2);
                        const int kBase = kk * 16 + (lane & 3) * 2;
                        float a0 = bs[(kBase + 0) * 132 + n];
                        float a1 = bs[(kBase + 1) * 132 + n];
                        split_pack(a0, a1, bHi[jj][0], bLo[jj][0]);
                        float a2 = bs[(kBase + 8) * 132 + n];
                        float a3 = bs[(kBase + 9) * 132 + n];
                        split_pack(a2, a3, bHi[jj][1], bLo[jj][1]);
                    }
                } else if (MODE == 2) {
                    // [n][k] rows of 68 floats; b0={B[n][k0+2t],B[n][k0+2t+1]}
#pragma unroll
                    for (int jj = 0; jj < 2; ++jj) {
                        const int n = wn + j4 * 16 + jj * 8 + (lane >> 2);
                        const int kBase = kk * 16 + (lane & 3) * 2;
                        float2 v0 = *(const float2*)(bs + n * 68 + kBase);
                        float2 v1 = *(const float2*)(bs + n * 68 + kBase + 8);
                        split_pack(v0.x, v0.y, bHi[jj][0], bLo[jj][0]);
                        split_pack(v1.x, v1.y, bHi[jj][1], bLo[jj][1]);
                    }
                } else {
                    // [k][n] rows of 268 floats
#pragma unroll
                    for (int jj = 0; jj < 2; ++jj) {
                        const int n = wn + j4 * 16 + jj * 8 + (lane >> 2);
                        const int kBase = kk * 16 + (lane & 3) * 2;
                        float a0 = bs[(kBase + 0) * 268 + n];
                        float a1 = bs[(kBase + 1) * 268 + n];
                        split_pack(a0, a1, bHi[jj][0], bLo[jj][0]);
                        float a2 = bs[(kBase + 8) * 268 + n];
                        float a3 = bs[(kBase + 9) * 268 + n];
                        split_pack(a2, a3, bHi[jj][1], bLo[jj][1]);
                    }
                }
                // term-major within group (acc dep distance 8)
#pragma unroll
                for (int i = 0; i < 4; ++i)
#pragma unroll
                    for (int jj = 0; jj < 2; ++jj)
                        mma_bf16(acc[i][j4 * 2 + jj], aHi[i], bHi[jj]);
#pragma unroll
                for (int i = 0; i < 4; ++i)
#pragma unroll
                    for (int jj = 0; jj < 2; ++jj)
                        mma_bf16(acc[i][j4 * 2 + jj], aHi[i], bLo[jj]);
#pragma unroll
                for (int i = 0; i < 4; ++i)
#pragma unroll
                    for (int jj = 0; jj < 2; ++jj)
                        mma_bf16(acc[i][j4 * 2 + jj], aLo[i], bHi[jj]);
            }
        }
        __syncthreads();
    }

    // Epilogue
    const int g = lane >> 2, t4 = lane & 3;
    const int colBase = (MODE == 1) ? x * 128 : x * 256;
#pragma unroll
    for (int i = 0; i < 4; ++i) {
#pragma unroll
        for (int j = 0; j < 8; ++j) {
            const int r0 = wm + i * 16 + g;
            const int r1 = r0 + 8;
            const int cc = colBase + wn + j * 8 + 2 * t4;
            if (MODE == 1) {
                const size_t o0 = (size_t)(y * 256 + r0) * kHID + cc;
                const size_t o1 = (size_t)(y * 256 + r1) * kHID + cc;
                uint32_t h, l;
                split_pack(acc[i][j][0], acc[i][j][1], h, l);
                *(uint32_t*)(g_Qhi + o0) = h;
                *(uint32_t*)(g_Qlo + o0) = l;
                split_pack(acc[i][j][2], acc[i][j][3], h, l);
                *(uint32_t*)(g_Qhi + o1) = h;
                *(uint32_t*)(g_Qlo + o1) = l;
            } else {
                float *o0, *o1;
                if (MODE == 2) {
                    o0 = g_P + (size_t)(y * 128 + r0) * kL + cc;
                    o1 = g_P + (size_t)(y * 128 + r1) * kL + cc;
                } else {
                    o0 = outP + (size_t)(y * 128 + r0) * kOut + kVEC + cc;
                    o1 = outP + (size_t)(y * 128 + r1) * kOut + kVEC + cc;
                }
                *(float2*)o0 = make_float2(acc[i][j][0], acc[i][j][1]);
                *(float2*)o1 = make_float2(acc[i][j][2], acc[i][j][3]);
            }
        }
    }
}

// ---------------------------------------------------------------------------
// Softmax over rows of g_P (8192 x 512) -> split bf16 attn g_Phi/g_Plo
// ---------------------------------------------------------------------------
__global__ void softmax_kernel() {
    const int lane = threadIdx.x & 31;
    const int warp = threadIdx.x >> 5;
    const int row = blockIdx.x * 8 + warp;
    const float4* p = (const float4*)(g_P + (size_t)row * kL);

    float4 v[4];
    float mx = -1e30f;
#pragma unroll
    for (int i = 0; i < 4; ++i) {
        v[i] = p[lane + 32 * i];
        mx = fmaxf(mx, fmaxf(fmaxf(v[i].x, v[i].y), fmaxf(v[i].z, v[i].w)));
    }
#pragma unroll
    for (int o = 16; o; o >>= 1) mx = fmaxf(mx, __shfl_xor_sync(0xffffffffu, mx, o));

    float sum = 0.f;
#pragma unroll
    for (int i = 0; i < 4; ++i) {
        v[i].x = __expf(v[i].x - mx); sum += v[i].x;
        v[i].y = __expf(v[i].y - mx); sum += v[i].y;
        v[i].z = __expf(v[i].z - mx); sum += v[i].z;
        v[i].w = __expf(v[i].w - mx); sum += v[i].w;
    }
#pragma unroll
    for (int o = 16; o; o >>= 1) sum += __shfl_xor_sync(0xffffffffu, sum, o);

    const float inv = 1.0f / sum;
#pragma unroll
    for (int i = 0; i < 4; ++i) {
        uint32_t h01, l01, h23, l23;
        split_pack(v[i].x * inv, v[i].y * inv, h01, l01);
        split_pack(v[i].z * inv, v[i].w * inv, h23, l23);
        size_t o = (size_t)row * kL + 4 * (lane + 32 * i);
        *(uint2*)(g_Phi + o) = make_uint2(h01, h23);
        *(uint2*)(g_Plo + o) = make_uint2(l01, l23);
    }
}

// ---------------------------------------------------------------------------
// Launch (probe folded into conv_sk; conv_W and conv_desc eliminated)
// ---------------------------------------------------------------------------
extern "C" void kernel_launch(void* const* d_in, const int* in_sizes, int n_in,
                              void* d_out, int out_size) {
    (void)in_sizes; (void)n_in; (void)out_size;
    const int*   s32  = (const int*)d_in[0];
    const float* desc = (const float*)d_in[1];
    const float* emb  = (const float*)d_in[2];
    const float* W    = (const float*)d_in[3];
    float* out = (float*)d_out;

    cudaFuncSetAttribute(mma_gemm<1>, cudaFuncAttributeMaxDynamicSharedMemorySize, 2 * Cfg<1>::STG);
    cudaFuncSetAttribute(mma_gemm<2>, cudaFuncAttributeMaxDynamicSharedMemorySize, 2 * Cfg<2>::STG);
    cudaFuncSetAttribute(mma_gemm<3>, cudaFuncAttributeMaxDynamicSharedMemorySize, 2 * Cfg<3>::STG);

    conv_sk<<<kRows, 128>>>(s32, emb, out);

    // GEMM1: Q[8192,1024], CTA 256x128 -> grid (8, 32); W split in-kernel
    mma_gemm<1><<<dim3(kHID / 128, kRows / 256), NT, 2 * Cfg<1>::STG>>>(nullptr, W);
    // GEMM2: scores[b][128,512], CTA 128x256 -> grid (2, 64); desc split in-kernel
    mma_gemm<2><<<dim3(kL / 256, kB), NT, 2 * Cfg<2>::STG>>>(nullptr, desc);
    softmax_kernel<<<kRows / 8, 256>>>();
    // GEMM3: ctx[b][128,1024], CTA 128x256 -> grid (4, 64); desc split in-kernel
    mma_gemm<3><<<dim3(kHID / 256, kB), NT, 2 * Cfg<3>::STG>>>(out, desc);
}

// round 17
// speedup vs baseline: 1.0288x; 1.0288x over previous
#include <cuda_runtime.h>
#include <cuda_bf16.h>
#include <cstdint>

// ---------------------------------------------------------------------------
// Problem constants
// ---------------------------------------------------------------------------
namespace {
constexpr int kB   = 64;
constexpr int kS   = 128;
constexpr int kL   = 512;
constexpr int kVEC = 512;
constexpr int kHID = 1024;
constexpr int kRows = kB * kS;          // 8192
constexpr int kOut  = kVEC + kHID;      // 1536

constexpr int NT = 256;                 // 8 warps per GEMM CTA

// Per-mode smem stage layout.
// MODE1: A bf16(256x128B x2 comp) + B bf16(128x128B x2 comp)   [pre-split W]
// MODE2: A bf16(128x128B x2 comp) + B fp32 desc [n][k] 256 rows x 68 floats
// MODE3: A bf16(128x128B x2 comp) + B fp32 desc [k][n] 64 rows x 268 floats
template<int MODE> struct Cfg;
template<> struct Cfg<1> {
    static constexpr int AR = 256, A_BYTES = 256 * 128;
    static constexpr int OFF_B = 2 * A_BYTES;
    static constexpr int STG = OFF_B + 2 * 16384;          // 98304
};
template<> struct Cfg<2> {
    static constexpr int AR = 128, A_BYTES = 128 * 128;
    static constexpr int OFF_B = 2 * A_BYTES;
    static constexpr int BROW = 68;                        // floats, 272B
    static constexpr int STG = OFF_B + 256 * BROW * 4;     // 102400
};
template<> struct Cfg<3> {
    static constexpr int AR = 128, A_BYTES = 128 * 128;
    static constexpr int OFF_B = 2 * A_BYTES;
    static constexpr int BROW = 268;                       // floats, 1072B
    static constexpr int STG = OFF_B + 64 * BROW * 4;      // 101376
};
}

// ---------------------------------------------------------------------------
// Device-global scratch (no allocations allowed)
// ---------------------------------------------------------------------------
#define DEVB __device__ __align__(16)
DEVB __nv_bfloat16 g_SKhi[(size_t)kRows * kVEC];
DEVB __nv_bfloat16 g_SKlo[(size_t)kRows * kVEC];
DEVB __nv_bfloat16 g_Wthi[(size_t)kHID * kVEC];        // W^T [1024,512]
DEVB __nv_bfloat16 g_Wtlo[(size_t)kHID * kVEC];
DEVB __nv_bfloat16 g_Qhi [(size_t)kRows * kHID];
DEVB __nv_bfloat16 g_Qlo [(size_t)kRows * kHID];
DEVB float         g_P   [(size_t)kRows * kL];         // scores (fp32)
DEVB __nv_bfloat16 g_Phi [(size_t)kRows * kL];         // attn split
DEVB __nv_bfloat16 g_Plo [(size_t)kRows * kL];

// ---------------------------------------------------------------------------
// Helpers
// ---------------------------------------------------------------------------
__device__ __forceinline__ uint32_t smem_u32(const void* p) {
    uint32_t a;
    asm("{ .reg .u64 t; cvta.to.shared.u64 t, %1; cvt.u32.u64 %0, t; }"
        : "=r"(a) : "l"(p));
    return a;
}
__device__ __forceinline__ uint32_t sw128(uint32_t off) {   // 128B rows
    return off ^ ((off >> 3) & 0x70);
}
__device__ __forceinline__ void ldsm_x4(uint32_t* r, uint32_t addr) {
    asm volatile("ldmatrix.sync.aligned.m8n8.x4.shared.b16 {%0,%1,%2,%3}, [%4];"
                 : "=r"(r[0]), "=r"(r[1]), "=r"(r[2]), "=r"(r[3]) : "r"(addr));
}
__device__ __forceinline__ void mma_bf16(float* c, const uint32_t* a, const uint32_t* b) {
    asm volatile(
        "mma.sync.aligned.m16n8k16.row.col.f32.bf16.bf16.f32 "
        "{%0,%1,%2,%3}, {%4,%5,%6,%7}, {%8,%9}, {%0,%1,%2,%3};"
        : "+f"(c[0]), "+f"(c[1]), "+f"(c[2]), "+f"(c[3])
        : "r"(a[0]), "r"(a[1]), "r"(a[2]), "r"(a[3]), "r"(b[0]), "r"(b[1]));
}
__device__ __forceinline__ void cpa16(uint32_t s, const void* g) {
    asm volatile("cp.async.cg.shared.global [%0], [%1], 16;" :: "r"(s), "l"(g));
}
__device__ __forceinline__ void cpa_commit() {
    asm volatile("cp.async.commit_group;" ::: "memory");
}
__device__ __forceinline__ void cpa_wait1() {
    asm volatile("cp.async.wait_group 1;" ::: "memory");
}
__device__ __forceinline__ void split2(float v, __nv_bfloat16& h, __nv_bfloat16& l) {
    h = __float2bfloat16(v);
    l = __float2bfloat16(v - __bfloat162float(h));
}
__device__ __forceinline__ void split_pack(float a, float b,
                                           uint32_t& hi, uint32_t& lo) {
    __nv_bfloat16 h0, h1, l0, l1;
    split2(a, h0, l0); split2(b, h1, l1);
    __nv_bfloat162 ph, pl;
    ph.x = h0; ph.y = h1; pl.x = l0; pl.y = l1;
    hi = *reinterpret_cast<uint32_t*>(&ph);
    lo = *reinterpret_cast<uint32_t*>(&pl);
}

// ---------------------------------------------------------------------------
// conv_sk: self-probing gather. Detects int64-vs-int32 skills per block
// (odd 32-bit words all zero <=> int64), then gathers emb rows into
// out[:,0:512] fp32 AND g_SKhi/lo bf16 split.
// ---------------------------------------------------------------------------
__global__ void conv_sk(const int* __restrict__ s32,
                        const float* __restrict__ emb,
                        float* __restrict__ out) {
    const int tx = threadIdx.x;               // 128 threads
    int w = (tx < 64) ? s32[2 * tx + 1] : 0;
    const int any = __syncthreads_or(w);
    const int row = blockIdx.x;
    const int idx = (any == 0) ? s32[2 * row] : s32[row];

    float4 v = ((const float4*)(emb + (size_t)idx * kVEC))[tx];
    ((float4*)(out + (size_t)row * kOut))[tx] = v;

    uint32_t h01, l01, h23, l23;
    split_pack(v.x, v.y, h01, l01);
    split_pack(v.z, v.w, h23, l23);
    size_t o = (size_t)row * kVEC + tx * 4;
    *(uint2*)(g_SKhi + o) = make_uint2(h01, h23);
    *(uint2*)(g_SKlo + o) = make_uint2(l01, l23);
}

// ---------------------------------------------------------------------------
// conv_W: transpose+split W[512,1024] -> Wt[1024,512] hi/lo
// ---------------------------------------------------------------------------
__global__ void conv_W(const float* __restrict__ W) {
    __shared__ float t[32][33];
    const int n0 = blockIdx.x * 32, k0 = blockIdx.y * 32;
    const int tx = threadIdx.x, ty = threadIdx.y;
#pragma unroll
    for (int i = 0; i < 4; ++i) {
        int k = k0 + ty + 8 * i;
        t[ty + 8 * i][tx] = W[(size_t)k * kHID + n0 + tx];
    }
    __syncthreads();
#pragma unroll
    for (int i = 0; i < 4; ++i) {
        int n = n0 + ty + 8 * i;
        float v = t[tx][ty + 8 * i];
        __nv_bfloat16 h, lo; split2(v, h, lo);
        g_Wthi[(size_t)n * kVEC + k0 + tx] = h;
        g_Wtlo[(size_t)n * kVEC + k0 + tx] = lo;
    }
}

// ---------------------------------------------------------------------------
// Split-bf16 warp-MMA GEMM, cp.async double-buffered, warp tile 64x64.
// MODE 1: CTA 256x128 (4Mx2N). Q = SK @ Wt^T.  B bf16 pre-split (ldmatrix).
// MODE 2: CTA 128x256 (2Mx4N). P = Q @ desc^T. B = fp32 desc [n][k] in smem;
//         fragments via LDS.float2 + split_pack (no conv_desc).
// MODE 3: CTA 128x256 (2Mx4N). ctx = attn @ desc. B = fp32 desc [k][n];
//         fragments via strided LDS + split_pack.
// ---------------------------------------------------------------------------
template<int MODE>
__global__ __launch_bounds__(NT, 1) void mma_gemm(float* __restrict__ outP,
                                                  const float* __restrict__ descp) {
    using C = Cfg<MODE>;
    extern __shared__ __align__(1024) char smem[];
    const uint32_t sb = smem_u32(smem);
    const int tid = threadIdx.x, wid = tid >> 5, lane = tid & 31;
    const int x = blockIdx.x, y = blockIdx.y;

    constexpr int K = (MODE == 2) ? kHID : kVEC;
    constexpr int STG = C::STG;

    const __nv_bfloat16 *Ahi, *Alo, *Bhi = nullptr, *Blo = nullptr;
    const float* Bf = nullptr;
    if (MODE == 1) {
        Ahi = g_SKhi + (size_t)y * 256 * K;  Alo = g_SKlo + (size_t)y * 256 * K;
        Bhi = g_Wthi + (size_t)x * 128 * K;  Blo = g_Wtlo + (size_t)x * 128 * K;
    } else if (MODE == 2) {
        Ahi = g_Qhi + (size_t)y * 128 * K;   Alo = g_Qlo + (size_t)y * 128 * K;
        Bf  = descp + (size_t)y * kL * kHID + (size_t)x * 256 * kHID;  // [n][k]
    } else {
        Ahi = g_Phi + (size_t)y * 128 * K;   Alo = g_Plo + (size_t)y * 128 * K;
        Bf  = descp + (size_t)y * kL * kHID;                           // [k][n]
    }

    const int wm = (MODE == 1) ? (wid >> 1) * 64 : (wid >> 2) * 64;
    const int wn = (MODE == 1) ? (wid & 1) * 64  : (wid & 3) * 64;

    auto load_stage = [&](int st, int k0) {
        const uint32_t so = sb + st * STG;
        // A: AR rows x 128B per component, sw128
#pragma unroll
        for (int it = 0; it < C::AR / 32; ++it) {
            const int ch = tid + it * NT;
            const int r = ch >> 3, c = ch & 7;
            const uint32_t d = sw128((uint32_t)(r * 128 + c * 16));
            const size_t go = (size_t)r * K + k0 + c * 8;
            cpa16(so + d, Ahi + go);
            cpa16(so + C::A_BYTES + d, Alo + go);
        }
        if (MODE == 1) {
            // B bf16: 128 n-rows x 128B per component, sw128
#pragma unroll
            for (int it = 0; it < 4; ++it) {
                const int ch = tid + it * NT;
                const int r = ch >> 3, c = ch & 7;
                const uint32_t d = sw128((uint32_t)(r * 128 + c * 16));
                const size_t go = (size_t)r * K + k0 + c * 8;
                cpa16(so + C::OFF_B + d, Bhi + go);
                cpa16(so + C::OFF_B + 16384 + d, Blo + go);
            }
        } else if (MODE == 2) {
            // B fp32 [n][k]: 256 rows x 64 floats (rows of 272B)
#pragma unroll
            for (int it = 0; it < 16; ++it) {
                const int ch = tid + it * NT;          // 0..4095
                const int r = ch >> 4, c = ch & 15;
                cpa16(so + C::OFF_B + r * 272 + c * 16,
                      Bf + (size_t)r * kHID + k0 + c * 4);
            }
        } else {
            // B fp32 [k][n]: 64 rows x 256 floats (rows of 1072B)
#pragma unroll
            for (int it = 0; it < 16; ++it) {
                const int ch = tid + it * NT;          // 0..4095
                const int r = ch >> 6, c = ch & 63;
                cpa16(so + C::OFF_B + r * 1072 + c * 16,
                      Bf + (size_t)(k0 + r) * kHID + x * 256 + c * 4);
            }
        }
    };

    float acc[4][8][4] = {};

    constexpr int NCH = K / 64;
    load_stage(0, 0);
    cpa_commit();

    for (int kc = 0; kc < NCH; ++kc) {
        const int st = kc & 1;
        if (kc + 1 < NCH) load_stage(st ^ 1, (kc + 1) * 64);
        cpa_commit();
        cpa_wait1();
        __syncthreads();

        const uint32_t so = sb + st * STG;
        const char* sp = smem + st * STG;
        const float* bs = (const float*)(sp + C::OFF_B);
#pragma unroll
        for (int kk = 0; kk < 4; ++kk) {
            // A fragments: 4 m-tiles x (hi,lo) via ldmatrix
            uint32_t aHi[4][4], aLo[4][4];
#pragma unroll
            for (int i = 0; i < 4; ++i) {
                const int row = wm + i * 16 + (lane & 15);
                const int kb  = kk * 32 + (lane >> 4) * 16;
                const uint32_t d = sw128((uint32_t)(row * 128 + kb));
                ldsm_x4(aHi[i], so + d);
                ldsm_x4(aLo[i], so + C::A_BYTES + d);
            }
            // B per 16-n group: build frags, fire 24 MMAs, move on.
#pragma unroll
            for (int j4 = 0; j4 < 4; ++j4) {
                uint32_t bHi[2][2], bLo[2][2];
                if (MODE == 1) {
                    const int row = wn + j4 * 16 + ((lane >> 4) & 1) * 8 + (lane & 7);
                    const int kb  = kk * 32 + ((lane >> 3) & 1) * 16;
                    const uint32_t d = sw128((uint32_t)(row * 128 + kb));
                    uint32_t r4[4];
                    ldsm_x4(r4, so + C::OFF_B + d);
                    bHi[0][0] = r4[0]; bHi[0][1] = r4[1];
                    bHi[1][0] = r4[2]; bHi[1][1] = r4[3];
                    ldsm_x4(r4, so + C::OFF_B + 16384 + d);
                    bLo[0][0] = r4[0]; bLo[0][1] = r4[1];
                    bLo[1][0] = r4[2]; bLo[1][1] = r4[3];
                } else if (MODE == 2) {
                    // [n][k] rows of 68 floats; b0={B[n][k0+2t],B[n][k0+2t+1]}
#pragma unroll
                    for (int jj = 0; jj < 2; ++jj) {
                        const int n = wn + j4 * 16 + jj * 8 + (lane >> 2);
                        const int kBase = kk * 16 + (lane & 3) * 2;
                        float2 v0 = *(const float2*)(bs + n * 68 + kBase);
                        float2 v1 = *(const float2*)(bs + n * 68 + kBase + 8);
                        split_pack(v0.x, v0.y, bHi[jj][0], bLo[jj][0]);
                        split_pack(v1.x, v1.y, bHi[jj][1], bLo[jj][1]);
                    }
                } else {
                    // [k][n] rows of 268 floats
#pragma unroll
                    for (int jj = 0; jj < 2; ++jj) {
                        const int n = wn + j4 * 16 + jj * 8 + (lane >> 2);
                        const int kBase = kk * 16 + (lane & 3) * 2;
                        float a0 = bs[(kBase + 0) * 268 + n];
                        float a1 = bs[(kBase + 1) * 268 + n];
                        split_pack(a0, a1, bHi[jj][0], bLo[jj][0]);
                        float a2 = bs[(kBase + 8) * 268 + n];
                        float a3 = bs[(kBase + 9) * 268 + n];
                        split_pack(a2, a3, bHi[jj][1], bLo[jj][1]);
                    }
                }
                // term-major within group (acc dep distance 8)
#pragma unroll
                for (int i = 0; i < 4; ++i)
#pragma unroll
                    for (int jj = 0; jj < 2; ++jj)
                        mma_bf16(acc[i][j4 * 2 + jj], aHi[i], bHi[jj]);
#pragma unroll
                for (int i = 0; i < 4; ++i)
#pragma unroll
                    for (int jj = 0; jj < 2; ++jj)
                        mma_bf16(acc[i][j4 * 2 + jj], aHi[i], bLo[jj]);
#pragma unroll
                for (int i = 0; i < 4; ++i)
#pragma unroll
                    for (int jj = 0; jj < 2; ++jj)
                        mma_bf16(acc[i][j4 * 2 + jj], aLo[i], bHi[jj]);
            }
        }
        __syncthreads();
    }

    // Epilogue
    const int g = lane >> 2, t4 = lane & 3;
    const int colBase = (MODE == 1) ? x * 128 : x * 256;
#pragma unroll
    for (int i = 0; i < 4; ++i) {
#pragma unroll
        for (int j = 0; j < 8; ++j) {
            const int r0 = wm + i * 16 + g;
            const int r1 = r0 + 8;
            const int cc = colBase + wn + j * 8 + 2 * t4;
            if (MODE == 1) {
                const size_t o0 = (size_t)(y * 256 + r0) * kHID + cc;
                const size_t o1 = (size_t)(y * 256 + r1) * kHID + cc;
                uint32_t h, l;
                split_pack(acc[i][j][0], acc[i][j][1], h, l);
                *(uint32_t*)(g_Qhi + o0) = h;
                *(uint32_t*)(g_Qlo + o0) = l;
                split_pack(acc[i][j][2], acc[i][j][3], h, l);
                *(uint32_t*)(g_Qhi + o1) = h;
                *(uint32_t*)(g_Qlo + o1) = l;
            } else {
                float *o0, *o1;
                if (MODE == 2) {
                    o0 = g_P + (size_t)(y * 128 + r0) * kL + cc;
                    o1 = g_P + (size_t)(y * 128 + r1) * kL + cc;
                } else {
                    o0 = outP + (size_t)(y * 128 + r0) * kOut + kVEC + cc;
                    o1 = outP + (size_t)(y * 128 + r1) * kOut + kVEC + cc;
                }
                *(float2*)o0 = make_float2(acc[i][j][0], acc[i][j][1]);
                *(float2*)o1 = make_float2(acc[i][j][2], acc[i][j][3]);
            }
        }
    }
}

// ---------------------------------------------------------------------------
// Softmax over rows of g_P (8192 x 512) -> split bf16 attn g_Phi/g_Plo
// ---------------------------------------------------------------------------
__global__ void softmax_kernel() {
    const int lane = threadIdx.x & 31;
    const int warp = threadIdx.x >> 5;
    const int row = blockIdx.x * 8 + warp;
    const float4* p = (const float4*)(g_P + (size_t)row * kL);

    float4 v[4];
    float mx = -1e30f;
#pragma unroll
    for (int i = 0; i < 4; ++i) {
        v[i] = p[lane + 32 * i];
        mx = fmaxf(mx, fmaxf(fmaxf(v[i].x, v[i].y), fmaxf(v[i].z, v[i].w)));
    }
#pragma unroll
    for (int o = 16; o; o >>= 1) mx = fmaxf(mx, __shfl_xor_sync(0xffffffffu, mx, o));

    float sum = 0.f;
#pragma unroll
    for (int i = 0; i < 4; ++i) {
        v[i].x = __expf(v[i].x - mx); sum += v[i].x;
        v[i].y = __expf(v[i].y - mx); sum += v[i].y;
        v[i].z = __expf(v[i].z - mx); sum += v[i].z;
        v[i].w = __expf(v[i].w - mx); sum += v[i].w;
    }
#pragma unroll
    for (int o = 16; o; o >>= 1) sum += __shfl_xor_sync(0xffffffffu, sum, o);

    const float inv = 1.0f / sum;
#pragma unroll
    for (int i = 0; i < 4; ++i) {
        uint32_t h01, l01, h23, l23;
        split_pack(v[i].x * inv, v[i].y * inv, h01, l01);
        split_pack(v[i].z * inv, v[i].w * inv, h23, l23);
        size_t o = (size_t)row * kL + 4 * (lane + 32 * i);
        *(uint2*)(g_Phi + o) = make_uint2(h01, h23);
        *(uint2*)(g_Plo + o) = make_uint2(l01, l23);
    }
}

// ---------------------------------------------------------------------------
// Launch (probe folded into conv_sk; conv_desc eliminated; conv_W restored)
// ---------------------------------------------------------------------------
extern "C" void kernel_launch(void* const* d_in, const int* in_sizes, int n_in,
                              void* d_out, int out_size) {
    (void)in_sizes; (void)n_in; (void)out_size;
    const int*   s32  = (const int*)d_in[0];
    const float* desc = (const float*)d_in[1];
    const float* emb  = (const float*)d_in[2];
    const float* W    = (const float*)d_in[3];
    float* out = (float*)d_out;

    cudaFuncSetAttribute(mma_gemm<1>, cudaFuncAttributeMaxDynamicSharedMemorySize, 2 * Cfg<1>::STG);
    cudaFuncSetAttribute(mma_gemm<2>, cudaFuncAttributeMaxDynamicSharedMemorySize, 2 * Cfg<2>::STG);
    cudaFuncSetAttribute(mma_gemm<3>, cudaFuncAttributeMaxDynamicSharedMemorySize, 2 * Cfg<3>::STG);

    conv_sk<<<kRows, 128>>>(s32, emb, out);
    conv_W<<<dim3(kHID / 32, kVEC / 32), dim3(32, 8)>>>(W);

    // GEMM1: Q[8192,1024], CTA 256x128 -> grid (8, 32); bf16 pre-split W
    mma_gemm<1><<<dim3(kHID / 128, kRows / 256), NT, 2 * Cfg<1>::STG>>>(nullptr, nullptr);
    // GEMM2: scores[b][128,512], CTA 128x256 -> grid (2, 64); desc split in-kernel
    mma_gemm<2><<<dim3(kL / 256, kB), NT, 2 * Cfg<2>::STG>>>(nullptr, desc);
    softmax_kernel<<<kRows / 8, 256>>>();
    // GEMM3: ctx[b][128,1024], CTA 128x256 -> grid (4, 64); desc split in-kernel
    mma_gemm<3><<<dim3(kHID / 256, kB), NT, 2 * Cfg<3>::STG>>>(out, desc);
}